// round 6
// baseline (speedup 1.0000x reference)
#include <cuda_runtime.h>
#include <cuda_fp16.h>
#include <stdint.h>

#define D      1024
#define NROWS  65536
#define DD     (D * D)

// ---- chain GEMM (128x128, BK=64, 3-stage) ----
#define TBK     64
#define KT      (D / TBK)            // 16
#define CSTAGE  32768                // (128+128) rows * 64 * 2B
#define CSMEM   (3 * CSTAGE + 1024)

// ---- big GEMM (256x128 CTA, 64x64 warp, BK=64, 3-stage) ----
#define BSTAGE  49152                // (256+128) rows * 64 * 2B
#define BSMEM   (3 * BSTAGE + 1024)

// ---------------- scratch -------------------------------------------------------
__device__ __half g_xh[(size_t)NROWS * D];
__device__ __half g_gh[(size_t)NROWS * D];
__device__ __half g_Ah  [2 * DD];   // 10A
__device__ __half g_Bneg[2 * DD];   // -10A
__device__ __half g_P2[2 * DD];
__device__ __half g_P3[2 * DD];
__device__ __half g_P4[2 * DD];
__device__ __half g_P5[2 * DD];
__device__ __half g_P6[2 * DD];
__device__ __half g_M [2 * DD];
__device__ float  g_part[2 * D];
__device__ float  g_pass[1];

__device__ __forceinline__ uint32_t smem_u32(const void* p) {
    return (uint32_t)__cvta_generic_to_shared(p);
}
#define LDSM_X4(r0, r1, r2, r3, addr) \
    asm volatile("ldmatrix.sync.aligned.m8n8.x4.shared.b16 {%0,%1,%2,%3}, [%4];" \
                 : "=r"(r0), "=r"(r1), "=r"(r2), "=r"(r3) : "r"(addr))
#define MMA16816(c0,c1,c2,c3,a0,a1,a2,a3,b0,b1) \
    asm volatile("mma.sync.aligned.m16n8k16.row.col.f32.f16.f16.f32 " \
        "{%0,%1,%2,%3}, {%4,%5,%6,%7}, {%8,%9}, {%0,%1,%2,%3};\n" \
        : "+f"(c0), "+f"(c1), "+f"(c2), "+f"(c3) \
        : "r"(a0), "r"(a1), "r"(a2), "r"(a3), "r"(b0), "r"(b1))

// ---------------- helpers -------------------------------------------------------

__global__ void convert_x_kernel(const float* __restrict__ x, __half* __restrict__ xh) {
    size_t i = ((size_t)blockIdx.x * blockDim.x + threadIdx.x) * 4;
    float4 v = *(const float4*)(x + i);
    *(__half2*)(xh + i)     = __floats2half2_rn(v.x, v.y);
    *(__half2*)(xh + i + 2) = __floats2half2_rn(v.z, v.w);
}

__global__ void skew_kernel(const float* __restrict__ W1, const float* __restrict__ W2,
                            __half* __restrict__ Ah, __half* __restrict__ Bneg) {
    int gidx = blockIdx.x * blockDim.x + threadIdx.x;
    int z = gidx >> 20;
    int idx = gidx & (DD - 1);
    const float* W = z ? W2 : W1;
    int i = idx >> 10, j = idx & (D - 1);
    float a = 5.0f * (W[idx] - W[j * D + i]);   // 10 * 0.5 * (W - W^T)
    Ah[gidx]   = __float2half(a);
    Bneg[gidx] = __float2half(-a);
}

// M = 0.2*Ah + 0.02*P2 + 2e-3*P3 + 2e-4*P4 + 2e-5*P5 + 1e-6*P6
__global__ void combine_kernel(const __half* __restrict__ Ah, const __half* __restrict__ P2,
                               const __half* __restrict__ P3, const __half* __restrict__ P4,
                               const __half* __restrict__ P5, const __half* __restrict__ P6,
                               __half* __restrict__ M) {
    size_t i = ((size_t)blockIdx.x * blockDim.x + threadIdx.x) * 2;
    float2 a  = __half22float2(*(const __half2*)&Ah[i]);
    float2 p2 = __half22float2(*(const __half2*)&P2[i]);
    float2 p3 = __half22float2(*(const __half2*)&P3[i]);
    float2 p4 = __half22float2(*(const __half2*)&P4[i]);
    float2 p5 = __half22float2(*(const __half2*)&P5[i]);
    float2 p6 = __half22float2(*(const __half2*)&P6[i]);
    float m0 = 0.2f*a.x + 0.02f*p2.x + 2e-3f*p3.x + 2e-4f*p4.x + 2e-5f*p5.x + 1e-6f*p6.x;
    float m1 = 0.2f*a.y + 0.02f*p2.y + 2e-3f*p3.y + 2e-4f*p4.y + 2e-5f*p5.y + 1e-6f*p6.y;
    *(__half2*)&M[i] = __floats2half2_rn(m0, m1);
}

__global__ void row_sum_kernel(const float* __restrict__ u1,
                               const float* __restrict__ u2,
                               float* __restrict__ part) {
    int b = blockIdx.x;
    const float* src = (b < D) ? (u1 + (size_t)b * D) : (u2 + (size_t)(b - D) * D);
    __shared__ float sm[256];
    float s = 0.f;
    for (int j = threadIdx.x; j < D; j += 256) s += src[j];
    sm[threadIdx.x] = s;
    __syncthreads();
    for (int o = 128; o > 0; o >>= 1) {
        if (threadIdx.x < o) sm[threadIdx.x] += sm[threadIdx.x + o];
        __syncthreads();
    }
    if (threadIdx.x == 0) part[b] = sm[0];
}

__global__ void pass_kernel(const float* __restrict__ part,
                            const float* __restrict__ theta,
                            float* __restrict__ out) {
    __shared__ float sm[1024];
    sm[threadIdx.x] = part[threadIdx.x] + part[threadIdx.x + 1024];
    __syncthreads();
    for (int o = 512; o > 0; o >>= 1) {
        if (threadIdx.x < o) sm[threadIdx.x] += sm[threadIdx.x + o];
        __syncthreads();
    }
    if (threadIdx.x == 0)
        out[0] = (sm[0] / 1048576.0f + theta[0]) * 1e-6f;
}

// ---------------- chain GEMM (power products): C = A @ B^T, plain fp16 store ----
// z mapping: layer = z&1, sel = z>>1.
//   Aop = Abase + layer*DD
//   Bop = (sel ? B2 : B1) + layer*DD
//   Out = (sel ? O2 : O1) + layer*DD
__global__ void __launch_bounds__(256, 2)
pow_gemm(const __half* __restrict__ Abase,
         const __half* __restrict__ B1, const __half* __restrict__ B2,
         __half* __restrict__ O1, __half* __restrict__ O2)
{
    extern __shared__ char dsm_raw[];
    char* dsm = (char*)(((uintptr_t)dsm_raw + 1023) & ~(uintptr_t)1023);
    const uint32_t sbase = smem_u32(dsm);

    const int tid  = threadIdx.x;
    const int w    = tid >> 5, lane = tid & 31;
    const int wr = w >> 2, wc = w & 3;
    const int grp = lane >> 2, q = lane & 3;
    const int lrow = lane & 15, lk = lane >> 4;

    const int zz = blockIdx.z;
    const size_t loff = (size_t)(zz & 1) * DD;
    const __half* A = Abase + loff;
    const __half* B = ((zz >> 1) ? B2 : B1) + loff;
    __half* P       = ((zz >> 1) ? O2 : O1) + loff;

    const size_t rowBase = (size_t)blockIdx.y * 128;
    const int    colBase = blockIdx.x * 128;

    float acc[4][4][4];
    #pragma unroll
    for (int a = 0; a < 4; a++)
        #pragma unroll
        for (int b = 0; b < 4; b++)
            #pragma unroll
            for (int c = 0; c < 4; c++) acc[a][b][c] = 0.f;

    auto load_tile = [&](int kt) {
        const int stage = kt % 3;
        const int k0 = kt * TBK;
        #pragma unroll
        for (int i = 0; i < 8; i++) {
            int id  = tid + (i << 8);
            int isB = id >> 10;
            int rc  = id & 1023;
            int row = rc >> 3, c = rc & 7;
            uint32_t sw = ((uint32_t)row << 7) | (((uint32_t)(c ^ (row & 7))) << 4);
            const __half* g = (isB ? (B + (size_t)(colBase + row) * D)
                                   : (A + (rowBase + row) * (size_t)D)) + k0 + (c << 3);
            uint32_t s = sbase + stage * CSTAGE + (isB << 14) + sw;
            asm volatile("cp.async.cg.shared.global [%0], [%1], 16;\n" :: "r"(s), "l"(g));
        }
        asm volatile("cp.async.commit_group;\n");
    };

    load_tile(0);
    load_tile(1);

    for (int kt = 0; kt < KT; kt++) {
        if (kt == KT - 1) asm volatile("cp.async.wait_group 0;\n");
        else              asm volatile("cp.async.wait_group 1;\n");
        __syncthreads();

        const uint32_t aS = sbase + (kt % 3) * CSTAGE;
        const uint32_t bS = aS + 16384;

        #pragma unroll
        for (int kp = 0; kp < 4; kp++) {
            const uint32_t ch = (uint32_t)(kp * 2 + lk);
            uint32_t a[4][4];
            #pragma unroll
            for (int mi = 0; mi < 4; mi++) {
                int row = wr * 64 + mi * 16 + lrow;
                uint32_t ad = aS + ((uint32_t)row << 7) + ((ch ^ (uint32_t)(row & 7)) << 4);
                LDSM_X4(a[mi][0], a[mi][1], a[mi][2], a[mi][3], ad);
            }
            uint32_t b[4][2];
            #pragma unroll
            for (int np = 0; np < 2; np++) {
                int row = wc * 32 + np * 16 + lrow;
                uint32_t bd = bS + ((uint32_t)row << 7) + ((ch ^ (uint32_t)(row & 7)) << 4);
                uint32_t r0, r1, r2, r3;
                LDSM_X4(r0, r1, r2, r3, bd);
                b[np * 2 + 0][0] = r0; b[np * 2 + 1][0] = r1;
                b[np * 2 + 0][1] = r2; b[np * 2 + 1][1] = r3;
            }
            #pragma unroll
            for (int mi = 0; mi < 4; mi++)
                #pragma unroll
                for (int ni = 0; ni < 4; ni++)
                    MMA16816(acc[mi][ni][0], acc[mi][ni][1], acc[mi][ni][2], acc[mi][ni][3],
                             a[mi][0], a[mi][1], a[mi][2], a[mi][3], b[ni][0], b[ni][1]);
        }
        if (kt + 2 < KT) load_tile(kt + 2);
    }

    #pragma unroll
    for (int mi = 0; mi < 4; mi++) {
        const int rloc = wr * 64 + mi * 16 + grp;
        #pragma unroll
        for (int rr = 0; rr < 2; rr++) {
            const size_t grow = rowBase + rloc + rr * 8;
            #pragma unroll
            for (int ni = 0; ni < 4; ni++) {
                const int gcol = colBase + wc * 32 + ni * 8 + q * 2;
                *(__half2*)&P[grow * D + gcol] =
                    __floats2half2_rn(acc[mi][ni][rr * 2], acc[mi][ni][rr * 2 + 1]);
            }
        }
    }
}

// ---------------- big GEMM: 256x128 CTA, 64x64 warp ----------------------------
// EPI 1: h = C + ident; rotate pairs by theta; OutH = half(h)
// EPI 2: OutF = C + ident + passv
template <int EPI>
__global__ void __launch_bounds__(256, 1)
big_gemm(const __half* __restrict__ Aop, const __half* __restrict__ Bop,
         const __half* __restrict__ ident, const float* __restrict__ theta,
         const float* __restrict__ passv,
         __half* __restrict__ OutH, float* __restrict__ OutF)
{
    extern __shared__ char dsm_raw[];
    char* dsm = (char*)(((uintptr_t)dsm_raw + 1023) & ~(uintptr_t)1023);
    const uint32_t sbase = smem_u32(dsm);

    const int tid  = threadIdx.x;
    const int w    = tid >> 5, lane = tid & 31;
    const int wr = w >> 1, wc = w & 1;            // 4 x 2 warp grid, 64x64 each
    const int grp = lane >> 2, q = lane & 3;
    const int lrow = lane & 15, lk = lane >> 4;

    const size_t rowBase = (size_t)blockIdx.y * 256;
    const int    colBase = blockIdx.x * 128;

    float acc[4][8][4];
    #pragma unroll
    for (int a = 0; a < 4; a++)
        #pragma unroll
        for (int b = 0; b < 8; b++)
            #pragma unroll
            for (int c = 0; c < 4; c++) acc[a][b][c] = 0.f;

    auto load_tile = [&](int kt) {
        const int stage = kt % 3;
        const int k0 = kt * TBK;
        #pragma unroll
        for (int i = 0; i < 12; i++) {
            int id  = tid + (i << 8);              // 0..3071 16B chunks
            int isB = (id >= 2048);
            int rc  = isB ? (id - 2048) : id;
            int row = rc >> 3, c = rc & 7;
            uint32_t sw = ((uint32_t)row << 7) | (((uint32_t)(c ^ (row & 7))) << 4);
            const __half* g = (isB ? (Bop + (size_t)(colBase + row) * D)
                                   : (Aop + (rowBase + row) * (size_t)D)) + k0 + (c << 3);
            uint32_t s = sbase + stage * BSTAGE + (isB ? 32768u : 0u) + sw;
            asm volatile("cp.async.cg.shared.global [%0], [%1], 16;\n" :: "r"(s), "l"(g));
        }
        asm volatile("cp.async.commit_group;\n");
    };

    load_tile(0);
    load_tile(1);

    for (int kt = 0; kt < KT; kt++) {
        if (kt == KT - 1) asm volatile("cp.async.wait_group 0;\n");
        else              asm volatile("cp.async.wait_group 1;\n");
        __syncthreads();

        const uint32_t aS = sbase + (kt % 3) * BSTAGE;
        const uint32_t bS = aS + 32768;

        #pragma unroll
        for (int kp = 0; kp < 4; kp++) {
            const uint32_t ch = (uint32_t)(kp * 2 + lk);
            uint32_t a[4][4];
            #pragma unroll
            for (int mi = 0; mi < 4; mi++) {
                int row = wr * 64 + mi * 16 + lrow;
                uint32_t ad = aS + ((uint32_t)row << 7) + ((ch ^ (uint32_t)(row & 7)) << 4);
                LDSM_X4(a[mi][0], a[mi][1], a[mi][2], a[mi][3], ad);
            }
            uint32_t b[8][2];
            #pragma unroll
            for (int np = 0; np < 4; np++) {
                int row = wc * 64 + np * 16 + lrow;
                uint32_t bd = bS + ((uint32_t)row << 7) + ((ch ^ (uint32_t)(row & 7)) << 4);
                uint32_t r0, r1, r2, r3;
                LDSM_X4(r0, r1, r2, r3, bd);
                b[np * 2 + 0][0] = r0; b[np * 2 + 1][0] = r1;
                b[np * 2 + 0][1] = r2; b[np * 2 + 1][1] = r3;
            }
            #pragma unroll
            for (int mi = 0; mi < 4; mi++)
                #pragma unroll
                for (int ni = 0; ni < 8; ni++)
                    MMA16816(acc[mi][ni][0], acc[mi][ni][1], acc[mi][ni][2], acc[mi][ni][3],
                             a[mi][0], a[mi][1], a[mi][2], a[mi][3], b[ni][0], b[ni][1]);
        }
        if (kt + 2 < KT) load_tile(kt + 2);
    }

    // ---------------- epilogue ----------------
    float cs = 0.f, sn = 0.f, pv = 0.f;
    if (EPI == 1) { float th = theta[0]; cs = cosf(th); sn = sinf(th); }
    if (EPI == 2) { pv = passv[0]; }

    #pragma unroll
    for (int mi = 0; mi < 4; mi++) {
        const int rloc = wr * 64 + mi * 16 + grp;
        #pragma unroll
        for (int rr = 0; rr < 2; rr++) {
            const size_t grow = rowBase + rloc + rr * 8;
            #pragma unroll
            for (int ni = 0; ni < 8; ni++) {
                const int gcol = colBase + wc * 64 + ni * 8 + q * 2;
                float v0 = acc[mi][ni][rr * 2 + 0];
                float v1 = acc[mi][ni][rr * 2 + 1];
                const size_t idx = grow * D + gcol;
                __half2 id = *(const __half2*)&ident[idx];
                if (EPI == 1) {
                    float h0 = v0 + __low2float(id);
                    float h1 = v1 + __high2float(id);
                    *(__half2*)&OutH[idx] = __floats2half2_rn(cs * h0 - sn * h1,
                                                              sn * h0 + cs * h1);
                } else {
                    float2 o;
                    o.x = v0 + __low2float(id) + pv;
                    o.y = v1 + __high2float(id) + pv;
                    *(float2*)&OutF[idx] = o;
                }
            }
        }
    }
}

// ---------------- host launcher ------------------------------------------------

extern "C" void kernel_launch(void* const* d_in, const int* in_sizes, int n_in,
                              void* d_out, int out_size) {
    const float* x     = (const float*)d_in[0];
    const float* u1    = (const float*)d_in[1];
    const float* u2    = (const float*)d_in[2];
    const float* theta = (const float*)d_in[3];
    float* out = (float*)d_out;

    __half *xh, *gh, *Ah, *Bneg, *P2, *P3, *P4, *P5, *P6, *M;
    float *part, *pass;
    cudaGetSymbolAddress((void**)&xh,   g_xh);
    cudaGetSymbolAddress((void**)&gh,   g_gh);
    cudaGetSymbolAddress((void**)&Ah,   g_Ah);
    cudaGetSymbolAddress((void**)&Bneg, g_Bneg);
    cudaGetSymbolAddress((void**)&P2,   g_P2);
    cudaGetSymbolAddress((void**)&P3,   g_P3);
    cudaGetSymbolAddress((void**)&P4,   g_P4);
    cudaGetSymbolAddress((void**)&P5,   g_P5);
    cudaGetSymbolAddress((void**)&P6,   g_P6);
    cudaGetSymbolAddress((void**)&M,    g_M);
    cudaGetSymbolAddress((void**)&part, g_part);
    cudaGetSymbolAddress((void**)&pass, g_pass);

    cudaFuncSetAttribute(pow_gemm,    cudaFuncAttributeMaxDynamicSharedMemorySize, CSMEM);
    cudaFuncSetAttribute(big_gemm<1>, cudaFuncAttributeMaxDynamicSharedMemorySize, BSMEM);
    cudaFuncSetAttribute(big_gemm<2>, cudaFuncAttributeMaxDynamicSharedMemorySize, BSMEM);

    // passthrough scalar
    row_sum_kernel<<<2 * D, 256>>>(u1, u2, part);
    pass_kernel<<<1, 1024>>>(part, theta, pass);

    // fp16 inputs
    convert_x_kernel<<<(int)(((size_t)NROWS * D) / 4 / 256), 256>>>(x, xh);

    // Neumann chain, depth 3 via power doubling (batched over layers in z)
    skew_kernel<<<2 * DD / 256, 256>>>(u1, u2, Ah, Bneg);
    pow_gemm<<<dim3(8, 8, 2), 256, CSMEM>>>(Ah, Bneg, Bneg, P2, P2);   // P2 = (10A)^2
    pow_gemm<<<dim3(8, 8, 4), 256, CSMEM>>>(P2, Bneg, P2, P3, P4);     // P3, P4 (P2 sym)
    pow_gemm<<<dim3(8, 8, 4), 256, CSMEM>>>(P4, Bneg, P2, P5, P6);     // P5, P6
    combine_kernel<<<2 * DD / 512, 256>>>(Ah, P2, P3, P4, P5, P6, M);

    // layer 1: g = rotate(x + x @ M1^T, theta)
    const dim3 gbig(D / 128, NROWS / 256);   // 8 x 256
    big_gemm<1><<<gbig, 256, BSMEM>>>(xh, M, xh, theta, nullptr, gh, nullptr);
    // layer 2: out = g + g @ M2^T + passthrough
    big_gemm<2><<<gbig, 256, BSMEM>>>(gh, M + DD, gh, nullptr, pass, nullptr, out);
}

// round 7
// speedup vs baseline: 1.0977x; 1.0977x over previous
#include <cuda_runtime.h>
#include <cuda_fp16.h>
#include <stdint.h>

#define D      1024
#define NROWS  65536
#define DD     (D * D)

// GEMM tile: 128x128, BK=64, 3-stage cp.async, ldmatrix + XOR swizzle
#define TBK     64
#define KT      (D / TBK)        // 16
#define STAGEB  32768            // (128 rows A + 128 rows B) * 64 halves * 2B
#define SMEMSZ  (3 * STAGEB + 1024)

// ---------------- scratch (static device globals; no allocations) -------------
__device__ __half g_xh[(size_t)NROWS * D];
__device__ __half g_gh[(size_t)NROWS * D];
__device__ __half g_Ah  [2 * DD];   // 10A
__device__ __half g_Bneg[2 * DD];   // -10A
__device__ __half g_P2[2 * DD];
__device__ __half g_P3[2 * DD];
__device__ __half g_P4[2 * DD];
__device__ __half g_P5[2 * DD];
__device__ __half g_P6[2 * DD];
__device__ __half g_M [2 * DD];
__device__ float  g_part[2 * D];
__device__ float  g_pass[1];

__device__ __forceinline__ uint32_t smem_u32(const void* p) {
    return (uint32_t)__cvta_generic_to_shared(p);
}
#define LDSM_X4(r0, r1, r2, r3, addr) \
    asm volatile("ldmatrix.sync.aligned.m8n8.x4.shared.b16 {%0,%1,%2,%3}, [%4];" \
                 : "=r"(r0), "=r"(r1), "=r"(r2), "=r"(r3) : "r"(addr))
#define MMA16816(c0,c1,c2,c3,a0,a1,a2,a3,b0,b1) \
    asm volatile("mma.sync.aligned.m16n8k16.row.col.f32.f16.f16.f32 " \
        "{%0,%1,%2,%3}, {%4,%5,%6,%7}, {%8,%9}, {%0,%1,%2,%3};\n" \
        : "+f"(c0), "+f"(c1), "+f"(c2), "+f"(c3) \
        : "r"(a0), "r"(a1), "r"(a2), "r"(a3), "r"(b0), "r"(b1))

// ---------------- helpers -------------------------------------------------------

__global__ void convert_x_kernel(const float* __restrict__ x, __half* __restrict__ xh) {
    size_t i = ((size_t)blockIdx.x * blockDim.x + threadIdx.x) * 4;
    float4 v = *(const float4*)(x + i);
    *(__half2*)(xh + i)     = __floats2half2_rn(v.x, v.y);
    *(__half2*)(xh + i + 2) = __floats2half2_rn(v.z, v.w);
}

__global__ void skew_kernel(const float* __restrict__ W1, const float* __restrict__ W2,
                            __half* __restrict__ Ah, __half* __restrict__ Bneg) {
    int gidx = blockIdx.x * blockDim.x + threadIdx.x;
    int z = gidx >> 20;
    int idx = gidx & (DD - 1);
    const float* W = z ? W2 : W1;
    int i = idx >> 10, j = idx & (D - 1);
    float a = 5.0f * (W[idx] - W[j * D + i]);   // 10 * 0.5 * (W - W^T)
    Ah[gidx]   = __float2half(a);
    Bneg[gidx] = __float2half(-a);
}

// M = 0.2*Ah + 0.02*P2 + 2e-3*P3 + 2e-4*P4 + 2e-5*P5 + 1e-6*P6
__global__ void combine_kernel(const __half* __restrict__ Ah, const __half* __restrict__ P2,
                               const __half* __restrict__ P3, const __half* __restrict__ P4,
                               const __half* __restrict__ P5, const __half* __restrict__ P6,
                               __half* __restrict__ M) {
    size_t i = ((size_t)blockIdx.x * blockDim.x + threadIdx.x) * 2;
    float2 a  = __half22float2(*(const __half2*)&Ah[i]);
    float2 p2 = __half22float2(*(const __half2*)&P2[i]);
    float2 p3 = __half22float2(*(const __half2*)&P3[i]);
    float2 p4 = __half22float2(*(const __half2*)&P4[i]);
    float2 p5 = __half22float2(*(const __half2*)&P5[i]);
    float2 p6 = __half22float2(*(const __half2*)&P6[i]);
    float m0 = 0.2f*a.x + 0.02f*p2.x + 2e-3f*p3.x + 2e-4f*p4.x + 2e-5f*p5.x + 1e-6f*p6.x;
    float m1 = 0.2f*a.y + 0.02f*p2.y + 2e-3f*p3.y + 2e-4f*p4.y + 2e-5f*p5.y + 1e-6f*p6.y;
    *(__half2*)&M[i] = __floats2half2_rn(m0, m1);
}

__global__ void row_sum_kernel(const float* __restrict__ u1,
                               const float* __restrict__ u2,
                               float* __restrict__ part) {
    int b = blockIdx.x;
    const float* src = (b < D) ? (u1 + (size_t)b * D) : (u2 + (size_t)(b - D) * D);
    __shared__ float sm[256];
    float s = 0.f;
    for (int j = threadIdx.x; j < D; j += 256) s += src[j];
    sm[threadIdx.x] = s;
    __syncthreads();
    for (int o = 128; o > 0; o >>= 1) {
        if (threadIdx.x < o) sm[threadIdx.x] += sm[threadIdx.x + o];
        __syncthreads();
    }
    if (threadIdx.x == 0) part[b] = sm[0];
}

__global__ void pass_kernel(const float* __restrict__ part,
                            const float* __restrict__ theta,
                            float* __restrict__ out) {
    __shared__ float sm[1024];
    sm[threadIdx.x] = part[threadIdx.x] + part[threadIdx.x + 1024];
    __syncthreads();
    for (int o = 512; o > 0; o >>= 1) {
        if (threadIdx.x < o) sm[threadIdx.x] += sm[threadIdx.x + o];
        __syncthreads();
    }
    if (threadIdx.x == 0)
        out[0] = (sm[0] / 1048576.0f + theta[0]) * 1e-6f;
}

// ---------------- unified HMMA GEMM core (128x128 CTA, 64x32 warp) --------------
// EPI 0 (POW) : P = half(C)                       (Neumann power product)
// EPI 1 (L1)  : h = C + ident; rotate by theta; OutH = half(h)
// EPI 2 (L2)  : OutF = C + ident + passv
template <int EPI>
__global__ void __launch_bounds__(256, 2)
gemm_ldsm(const __half* __restrict__ Aop, const __half* __restrict__ Bop,
          __half* __restrict__ Ph,
          const __half* __restrict__ ident, const float* __restrict__ theta,
          const float* __restrict__ passv, float* __restrict__ OutF,
          const __half* __restrict__ B2, __half* __restrict__ O2)
{
    extern __shared__ char dsm_raw[];
    char* dsm = (char*)(((uintptr_t)dsm_raw + 1023) & ~(uintptr_t)1023);
    const uint32_t sbase = smem_u32(dsm);

    const int tid  = threadIdx.x;
    const int w    = tid >> 5, lane = tid & 31;
    const int wr = w >> 2, wc = w & 3;            // 2 x 4 warp grid -> 64x32 per warp
    const int grp = lane >> 2, q = lane & 3;
    const int lrow = lane & 15, lk = lane >> 4;

    // chain batching: layer = z&1, operand/output select = z>>1 (EPI 0 only)
    const __half* A;
    const __half* B;
    __half* P = nullptr;
    if (EPI == 0) {
        const int zz = blockIdx.z;
        const size_t loff = (size_t)(zz & 1) * DD;
        A = Aop + loff;
        B = ((zz >> 1) ? B2 : Bop) + loff;
        P = ((zz >> 1) ? O2 : Ph) + loff;
    } else {
        A = Aop; B = Bop; P = Ph;
    }

    const size_t rowBase = (size_t)blockIdx.y * 128;
    const int    colBase = blockIdx.x * 128;

    float acc[4][4][4];
    #pragma unroll
    for (int a = 0; a < 4; a++)
        #pragma unroll
        for (int b = 0; b < 4; b++)
            #pragma unroll
            for (int c = 0; c < 4; c++) acc[a][b][c] = 0.f;

    auto load_tile = [&](int kt) {
        const int stage = kt % 3;
        const int k0 = kt * TBK;
        #pragma unroll
        for (int i = 0; i < 8; i++) {
            int id  = tid + (i << 8);              // 0..2047 16B chunks
            int isB = id >> 10;
            int rc  = id & 1023;
            int row = rc >> 3, c = rc & 7;
            uint32_t sw = ((uint32_t)row << 7) | (((uint32_t)(c ^ (row & 7))) << 4);
            const __half* g = (isB ? (B + (size_t)(colBase + row) * D)
                                   : (A + (rowBase + row) * (size_t)D)) + k0 + (c << 3);
            uint32_t s = sbase + stage * STAGEB + (isB << 14) + sw;
            asm volatile("cp.async.cg.shared.global [%0], [%1], 16;\n" :: "r"(s), "l"(g));
        }
        asm volatile("cp.async.commit_group;\n");
    };

    load_tile(0);
    load_tile(1);

    for (int kt = 0; kt < KT; kt++) {
        if (kt == KT - 1) asm volatile("cp.async.wait_group 0;\n");
        else              asm volatile("cp.async.wait_group 1;\n");
        __syncthreads();

        const uint32_t aS = sbase + (kt % 3) * STAGEB;
        const uint32_t bS = aS + 16384;

        #pragma unroll
        for (int kp = 0; kp < 4; kp++) {
            const uint32_t ch = (uint32_t)(kp * 2 + lk);
            uint32_t a[4][4];
            #pragma unroll
            for (int mi = 0; mi < 4; mi++) {
                int row = wr * 64 + mi * 16 + lrow;
                uint32_t ad = aS + ((uint32_t)row << 7) + ((ch ^ (uint32_t)(row & 7)) << 4);
                LDSM_X4(a[mi][0], a[mi][1], a[mi][2], a[mi][3], ad);
            }
            uint32_t b[4][2];
            #pragma unroll
            for (int np = 0; np < 2; np++) {
                int row = wc * 32 + np * 16 + lrow;
                uint32_t bd = bS + ((uint32_t)row << 7) + ((ch ^ (uint32_t)(row & 7)) << 4);
                uint32_t r0, r1, r2, r3;
                LDSM_X4(r0, r1, r2, r3, bd);
                b[np * 2 + 0][0] = r0; b[np * 2 + 1][0] = r1;
                b[np * 2 + 0][1] = r2; b[np * 2 + 1][1] = r3;
            }
            #pragma unroll
            for (int mi = 0; mi < 4; mi++)
                #pragma unroll
                for (int ni = 0; ni < 4; ni++)
                    MMA16816(acc[mi][ni][0], acc[mi][ni][1], acc[mi][ni][2], acc[mi][ni][3],
                             a[mi][0], a[mi][1], a[mi][2], a[mi][3], b[ni][0], b[ni][1]);
        }
        if (kt + 2 < KT) load_tile(kt + 2);
    }

    // ---------------- epilogue ----------------
    float cs = 0.f, sn = 0.f, pv = 0.f;
    if (EPI == 1) { float th = theta[0]; cs = cosf(th); sn = sinf(th); }
    if (EPI == 2) { pv = passv[0]; }

    #pragma unroll
    for (int mi = 0; mi < 4; mi++) {
        const int rloc = wr * 64 + mi * 16 + grp;
        #pragma unroll
        for (int rr = 0; rr < 2; rr++) {
            const size_t grow = rowBase + rloc + rr * 8;
            #pragma unroll
            for (int ni = 0; ni < 4; ni++) {
                const int gcol = colBase + wc * 32 + ni * 8 + q * 2;
                float v0 = acc[mi][ni][rr * 2 + 0];
                float v1 = acc[mi][ni][rr * 2 + 1];
                const size_t idx = grow * D + gcol;
                if (EPI == 0) {
                    *(__half2*)&P[idx] = __floats2half2_rn(v0, v1);
                } else if (EPI == 1) {
                    __half2 id = *(const __half2*)&ident[idx];
                    float h0 = v0 + __low2float(id);
                    float h1 = v1 + __high2float(id);
                    *(__half2*)&P[idx] = __floats2half2_rn(cs * h0 - sn * h1,
                                                           sn * h0 + cs * h1);
                } else {
                    __half2 id = *(const __half2*)&ident[idx];
                    float2 o;
                    o.x = v0 + __low2float(id) + pv;
                    o.y = v1 + __high2float(id) + pv;
                    *(float2*)&OutF[idx] = o;
                }
            }
        }
    }
}

// ---------------- host launcher ------------------------------------------------

extern "C" void kernel_launch(void* const* d_in, const int* in_sizes, int n_in,
                              void* d_out, int out_size) {
    const float* x     = (const float*)d_in[0];
    const float* u1    = (const float*)d_in[1];
    const float* u2    = (const float*)d_in[2];
    const float* theta = (const float*)d_in[3];
    float* out = (float*)d_out;

    __half *xh, *gh, *Ah, *Bneg, *P2, *P3, *P4, *P5, *P6, *M;
    float *part, *pass;
    cudaGetSymbolAddress((void**)&xh,   g_xh);
    cudaGetSymbolAddress((void**)&gh,   g_gh);
    cudaGetSymbolAddress((void**)&Ah,   g_Ah);
    cudaGetSymbolAddress((void**)&Bneg, g_Bneg);
    cudaGetSymbolAddress((void**)&P2,   g_P2);
    cudaGetSymbolAddress((void**)&P3,   g_P3);
    cudaGetSymbolAddress((void**)&P4,   g_P4);
    cudaGetSymbolAddress((void**)&P5,   g_P5);
    cudaGetSymbolAddress((void**)&P6,   g_P6);
    cudaGetSymbolAddress((void**)&M,    g_M);
    cudaGetSymbolAddress((void**)&part, g_part);
    cudaGetSymbolAddress((void**)&pass, g_pass);

    cudaFuncSetAttribute(gemm_ldsm<0>, cudaFuncAttributeMaxDynamicSharedMemorySize, SMEMSZ);
    cudaFuncSetAttribute(gemm_ldsm<1>, cudaFuncAttributeMaxDynamicSharedMemorySize, SMEMSZ);
    cudaFuncSetAttribute(gemm_ldsm<2>, cudaFuncAttributeMaxDynamicSharedMemorySize, SMEMSZ);

    // passthrough scalar
    row_sum_kernel<<<2 * D, 256>>>(u1, u2, part);
    pass_kernel<<<1, 1024>>>(part, theta, pass);

    // fp16 inputs
    convert_x_kernel<<<(int)(((size_t)NROWS * D) / 4 / 256), 256>>>(x, xh);

    // Neumann chain, depth 3 via power doubling (batched over layers in z)
    skew_kernel<<<2 * DD / 256, 256>>>(u1, u2, Ah, Bneg);
    // P2 = (10A)^2
    gemm_ldsm<0><<<dim3(8, 8, 2), 256, SMEMSZ>>>(Ah, Bneg, P2, nullptr, nullptr, nullptr, nullptr, Bneg, P2);
    // P3 = P2 @ (10A) [via Bneg^T], P4 = P2 @ P2 (P2 symmetric)
    gemm_ldsm<0><<<dim3(8, 8, 4), 256, SMEMSZ>>>(P2, Bneg, P3, nullptr, nullptr, nullptr, nullptr, P2, P4);
    // P5 = P4 @ (10A), P6 = P4 @ P2
    gemm_ldsm<0><<<dim3(8, 8, 4), 256, SMEMSZ>>>(P4, Bneg, P5, nullptr, nullptr, nullptr, nullptr, P2, P6);
    combine_kernel<<<2 * DD / 512, 256>>>(Ah, P2, P3, P4, P5, P6, M);

    // layer 1: g = rotate(x + x @ M1^T, theta)
    const dim3 gbig(D / 128, NROWS / 128);   // 8 x 512
    gemm_ldsm<1><<<gbig, 256, SMEMSZ>>>(xh, M, gh, xh, theta, nullptr, nullptr, nullptr, nullptr);
    // layer 2: out = g + g @ M2^T + passthrough
    gemm_ldsm<2><<<gbig, 256, SMEMSZ>>>(gh, M + DD, nullptr, gh, nullptr, pass, out, nullptr, nullptr);
}

// round 8
// speedup vs baseline: 1.1186x; 1.0191x over previous
#include <cuda_runtime.h>
#include <cuda_fp16.h>
#include <stdint.h>

#define D      1024
#define NROWS  65536
#define DD     (D * D)

// GEMM tile: 128x128, BK=64, 3-stage cp.async, ldmatrix + XOR swizzle
#define TBK     64
#define KT      (D / TBK)        // 16
#define STAGEB  32768            // (128 rows A + 128 rows B) * 64 halves * 2B
#define SMEMSZ  (3 * STAGEB + 1024)

// ---------------- scratch (static device globals; no allocations) -------------
__device__ __half g_xh[(size_t)NROWS * D];
__device__ __half g_gh[(size_t)NROWS * D];
__device__ __half g_Ah  [2 * DD];   // 10A
__device__ __half g_Bneg[2 * DD];   // -10A
__device__ __half g_P2[2 * DD];
__device__ __half g_P3[2 * DD];
__device__ __half g_P4[2 * DD];
__device__ __half g_M [2 * DD];
__device__ float  g_part[2 * D];
__device__ float  g_pass[1];

__device__ __forceinline__ uint32_t smem_u32(const void* p) {
    return (uint32_t)__cvta_generic_to_shared(p);
}
#define LDSM_X4(r0, r1, r2, r3, addr) \
    asm volatile("ldmatrix.sync.aligned.m8n8.x4.shared.b16 {%0,%1,%2,%3}, [%4];" \
                 : "=r"(r0), "=r"(r1), "=r"(r2), "=r"(r3) : "r"(addr))
#define MMA16816(c0,c1,c2,c3,a0,a1,a2,a3,b0,b1) \
    asm volatile("mma.sync.aligned.m16n8k16.row.col.f32.f16.f16.f32 " \
        "{%0,%1,%2,%3}, {%4,%5,%6,%7}, {%8,%9}, {%0,%1,%2,%3};\n" \
        : "+f"(c0), "+f"(c1), "+f"(c2), "+f"(c3) \
        : "r"(a0), "r"(a1), "r"(a2), "r"(a3), "r"(b0), "r"(b1))

// ---------------- helpers -------------------------------------------------------

__global__ void convert_x_kernel(const float* __restrict__ x, __half* __restrict__ xh) {
    size_t i = ((size_t)blockIdx.x * blockDim.x + threadIdx.x) * 4;
    float4 v = *(const float4*)(x + i);
    *(__half2*)(xh + i)     = __floats2half2_rn(v.x, v.y);
    *(__half2*)(xh + i + 2) = __floats2half2_rn(v.z, v.w);
}

__global__ void skew_kernel(const float* __restrict__ W1, const float* __restrict__ W2,
                            __half* __restrict__ Ah, __half* __restrict__ Bneg) {
    int gidx = blockIdx.x * blockDim.x + threadIdx.x;
    int z = gidx >> 20;
    int idx = gidx & (DD - 1);
    const float* W = z ? W2 : W1;
    int i = idx >> 10, j = idx & (D - 1);
    float a = 5.0f * (W[idx] - W[j * D + i]);   // 10 * 0.5 * (W - W^T)
    Ah[gidx]   = __float2half(a);
    Bneg[gidx] = __float2half(-a);
}

// M = 0.2*Ah + 0.02*P2 + 2e-3*P3 + 2e-4*P4   (A^5, A^6 terms < 2e-5 of M; dropped)
__global__ void combine_kernel(const __half* __restrict__ Ah, const __half* __restrict__ P2,
                               const __half* __restrict__ P3, const __half* __restrict__ P4,
                               __half* __restrict__ M) {
    size_t i = ((size_t)blockIdx.x * blockDim.x + threadIdx.x) * 2;
    float2 a  = __half22float2(*(const __half2*)&Ah[i]);
    float2 p2 = __half22float2(*(const __half2*)&P2[i]);
    float2 p3 = __half22float2(*(const __half2*)&P3[i]);
    float2 p4 = __half22float2(*(const __half2*)&P4[i]);
    float m0 = 0.2f*a.x + 0.02f*p2.x + 2e-3f*p3.x + 2e-4f*p4.x;
    float m1 = 0.2f*a.y + 0.02f*p2.y + 2e-3f*p3.y + 2e-4f*p4.y;
    *(__half2*)&M[i] = __floats2half2_rn(m0, m1);
}

__global__ void row_sum_kernel(const float* __restrict__ u1,
                               const float* __restrict__ u2,
                               float* __restrict__ part) {
    int b = blockIdx.x;
    const float* src = (b < D) ? (u1 + (size_t)b * D) : (u2 + (size_t)(b - D) * D);
    __shared__ float sm[256];
    float s = 0.f;
    for (int j = threadIdx.x; j < D; j += 256) s += src[j];
    sm[threadIdx.x] = s;
    __syncthreads();
    for (int o = 128; o > 0; o >>= 1) {
        if (threadIdx.x < o) sm[threadIdx.x] += sm[threadIdx.x + o];
        __syncthreads();
    }
    if (threadIdx.x == 0) part[b] = sm[0];
}

__global__ void pass_kernel(const float* __restrict__ part,
                            const float* __restrict__ theta,
                            float* __restrict__ out) {
    __shared__ float sm[1024];
    sm[threadIdx.x] = part[threadIdx.x] + part[threadIdx.x + 1024];
    __syncthreads();
    for (int o = 512; o > 0; o >>= 1) {
        if (threadIdx.x < o) sm[threadIdx.x] += sm[threadIdx.x + o];
        __syncthreads();
    }
    if (threadIdx.x == 0)
        out[0] = (sm[0] / 1048576.0f + theta[0]) * 1e-6f;
}

// ---------------- unified HMMA GEMM core (128x128 CTA, 64x32 warp) --------------
// EPI 0 (POW) : P = half(C)                       (Neumann power product)
// EPI 1 (L1)  : h = C + ident; rotate by theta; OutH = half(h)
// EPI 2 (L2)  : OutF = C + ident + passv
template <int EPI>
__global__ void __launch_bounds__(256, 2)
gemm_ldsm(const __half* __restrict__ Aop, const __half* __restrict__ Bop,
          __half* __restrict__ Ph,
          const __half* __restrict__ ident, const float* __restrict__ theta,
          const float* __restrict__ passv, float* __restrict__ OutF,
          const __half* __restrict__ B2, __half* __restrict__ O2)
{
    extern __shared__ char dsm_raw[];
    char* dsm = (char*)(((uintptr_t)dsm_raw + 1023) & ~(uintptr_t)1023);
    const uint32_t sbase = smem_u32(dsm);

    const int tid  = threadIdx.x;
    const int w    = tid >> 5, lane = tid & 31;
    const int wr = w >> 2, wc = w & 3;            // 2 x 4 warp grid -> 64x32 per warp
    const int grp = lane >> 2, q = lane & 3;
    const int lrow = lane & 15, lk = lane >> 4;

    // chain batching: layer = z&1, operand/output select = z>>1 (EPI 0 only)
    const __half* A;
    const __half* B;
    __half* P = nullptr;
    if (EPI == 0) {
        const int zz = blockIdx.z;
        const size_t loff = (size_t)(zz & 1) * DD;
        A = Aop + loff;
        B = ((zz >> 1) ? B2 : Bop) + loff;
        P = ((zz >> 1) ? O2 : Ph) + loff;
    } else {
        A = Aop; B = Bop; P = Ph;
    }

    const size_t rowBase = (size_t)blockIdx.y * 128;
    const int    colBase = blockIdx.x * 128;

    float acc[4][4][4];
    #pragma unroll
    for (int a = 0; a < 4; a++)
        #pragma unroll
        for (int b = 0; b < 4; b++)
            #pragma unroll
            for (int c = 0; c < 4; c++) acc[a][b][c] = 0.f;

    auto load_tile = [&](int kt) {
        const int stage = kt % 3;
        const int k0 = kt * TBK;
        #pragma unroll
        for (int i = 0; i < 8; i++) {
            int id  = tid + (i << 8);              // 0..2047 16B chunks
            int isB = id >> 10;
            int rc  = id & 1023;
            int row = rc >> 3, c = rc & 7;
            uint32_t sw = ((uint32_t)row << 7) | (((uint32_t)(c ^ (row & 7))) << 4);
            const __half* g = (isB ? (B + (size_t)(colBase + row) * D)
                                   : (A + (rowBase + row) * (size_t)D)) + k0 + (c << 3);
            uint32_t s = sbase + stage * STAGEB + (isB << 14) + sw;
            asm volatile("cp.async.cg.shared.global [%0], [%1], 16;\n" :: "r"(s), "l"(g));
        }
        asm volatile("cp.async.commit_group;\n");
    };

    load_tile(0);
    load_tile(1);

    for (int kt = 0; kt < KT; kt++) {
        if (kt == KT - 1) asm volatile("cp.async.wait_group 0;\n");
        else              asm volatile("cp.async.wait_group 1;\n");
        __syncthreads();

        // issue next prefetch BEFORE compute so the copy overlaps the MMAs
        // (stage (kt+2)%3 was last read in iteration kt-1 -> free)
        if (kt + 2 < KT) load_tile(kt + 2);

        const uint32_t aS = sbase + (kt % 3) * STAGEB;
        const uint32_t bS = aS + 16384;

        #pragma unroll
        for (int kp = 0; kp < 4; kp++) {
            const uint32_t ch = (uint32_t)(kp * 2 + lk);
            uint32_t a[4][4];
            #pragma unroll
            for (int mi = 0; mi < 4; mi++) {
                int row = wr * 64 + mi * 16 + lrow;
                uint32_t ad = aS + ((uint32_t)row << 7) + ((ch ^ (uint32_t)(row & 7)) << 4);
                LDSM_X4(a[mi][0], a[mi][1], a[mi][2], a[mi][3], ad);
            }
            uint32_t b[4][2];
            #pragma unroll
            for (int np = 0; np < 2; np++) {
                int row = wc * 32 + np * 16 + lrow;
                uint32_t bd = bS + ((uint32_t)row << 7) + ((ch ^ (uint32_t)(row & 7)) << 4);
                uint32_t r0, r1, r2, r3;
                LDSM_X4(r0, r1, r2, r3, bd);
                b[np * 2 + 0][0] = r0; b[np * 2 + 1][0] = r1;
                b[np * 2 + 0][1] = r2; b[np * 2 + 1][1] = r3;
            }
            #pragma unroll
            for (int mi = 0; mi < 4; mi++)
                #pragma unroll
                for (int ni = 0; ni < 4; ni++)
                    MMA16816(acc[mi][ni][0], acc[mi][ni][1], acc[mi][ni][2], acc[mi][ni][3],
                             a[mi][0], a[mi][1], a[mi][2], a[mi][3], b[ni][0], b[ni][1]);
        }
    }

    // ---------------- epilogue ----------------
    float cs = 0.f, sn = 0.f, pv = 0.f;
    if (EPI == 1) { float th = theta[0]; cs = cosf(th); sn = sinf(th); }
    if (EPI == 2) { pv = passv[0]; }

    #pragma unroll
    for (int mi = 0; mi < 4; mi++) {
        const int rloc = wr * 64 + mi * 16 + grp;
        #pragma unroll
        for (int rr = 0; rr < 2; rr++) {
            const size_t grow = rowBase + rloc + rr * 8;
            #pragma unroll
            for (int ni = 0; ni < 4; ni++) {
                const int gcol = colBase + wc * 32 + ni * 8 + q * 2;
                float v0 = acc[mi][ni][rr * 2 + 0];
                float v1 = acc[mi][ni][rr * 2 + 1];
                const size_t idx = grow * D + gcol;
                if (EPI == 0) {
                    *(__half2*)&P[idx] = __floats2half2_rn(v0, v1);
                } else if (EPI == 1) {
                    __half2 id = *(const __half2*)&ident[idx];
                    float h0 = v0 + __low2float(id);
                    float h1 = v1 + __high2float(id);
                    *(__half2*)&P[idx] = __floats2half2_rn(cs * h0 - sn * h1,
                                                           sn * h0 + cs * h1);
                } else {
                    __half2 id = *(const __half2*)&ident[idx];
                    float2 o;
                    o.x = v0 + __low2float(id) + pv;
                    o.y = v1 + __high2float(id) + pv;
                    *(float2*)&OutF[idx] = o;
                }
            }
        }
    }
}

// ---------------- host launcher ------------------------------------------------

extern "C" void kernel_launch(void* const* d_in, const int* in_sizes, int n_in,
                              void* d_out, int out_size) {
    const float* x     = (const float*)d_in[0];
    const float* u1    = (const float*)d_in[1];
    const float* u2    = (const float*)d_in[2];
    const float* theta = (const float*)d_in[3];
    float* out = (float*)d_out;

    __half *xh, *gh, *Ah, *Bneg, *P2, *P3, *P4, *M;
    float *part, *pass;
    cudaGetSymbolAddress((void**)&xh,   g_xh);
    cudaGetSymbolAddress((void**)&gh,   g_gh);
    cudaGetSymbolAddress((void**)&Ah,   g_Ah);
    cudaGetSymbolAddress((void**)&Bneg, g_Bneg);
    cudaGetSymbolAddress((void**)&P2,   g_P2);
    cudaGetSymbolAddress((void**)&P3,   g_P3);
    cudaGetSymbolAddress((void**)&P4,   g_P4);
    cudaGetSymbolAddress((void**)&M,    g_M);
    cudaGetSymbolAddress((void**)&part, g_part);
    cudaGetSymbolAddress((void**)&pass, g_pass);

    cudaFuncSetAttribute(gemm_ldsm<0>, cudaFuncAttributeMaxDynamicSharedMemorySize, SMEMSZ);
    cudaFuncSetAttribute(gemm_ldsm<1>, cudaFuncAttributeMaxDynamicSharedMemorySize, SMEMSZ);
    cudaFuncSetAttribute(gemm_ldsm<2>, cudaFuncAttributeMaxDynamicSharedMemorySize, SMEMSZ);

    // passthrough scalar
    row_sum_kernel<<<2 * D, 256>>>(u1, u2, part);
    pass_kernel<<<1, 1024>>>(part, theta, pass);

    // fp16 inputs
    convert_x_kernel<<<(int)(((size_t)NROWS * D) / 4 / 256), 256>>>(x, xh);

    // Neumann chain (terms through A^4; A^5/A^6 contribute <2e-5 relative to M)
    skew_kernel<<<2 * DD / 256, 256>>>(u1, u2, Ah, Bneg);
    // P2 = (10A)^2
    gemm_ldsm<0><<<dim3(8, 8, 2), 256, SMEMSZ>>>(Ah, Bneg, P2, nullptr, nullptr, nullptr, nullptr, Bneg, P2);
    // P3 = P2 @ (10A) [via Bneg^T], P4 = P2 @ P2 (P2 symmetric)
    gemm_ldsm<0><<<dim3(8, 8, 4), 256, SMEMSZ>>>(P2, Bneg, P3, nullptr, nullptr, nullptr, nullptr, P2, P4);
    combine_kernel<<<2 * DD / 512, 256>>>(Ah, P2, P3, P4, M);

    // layer 1: g = rotate(x + x @ M1^T, theta)
    const dim3 gbig(D / 128, NROWS / 128);   // 8 x 512
    gemm_ldsm<1><<<gbig, 256, SMEMSZ>>>(xh, M, gh, xh, theta, nullptr, nullptr, nullptr, nullptr);
    // layer 2: out = g + g @ M2^T + passthrough
    gemm_ldsm<2><<<gbig, 256, SMEMSZ>>>(gh, M + DD, nullptr, gh, nullptr, pass, out, nullptr, nullptr);
}